// round 2
// baseline (speedup 1.0000x reference)
#include <cuda_runtime.h>

#define D1 160
#define D2 192
#define D3 224

static constexpr int NVOX = D1 * D2 * D3;   // 6,881,280

// Fetch both z-corners of one (x,y) row with 128-bit loads.
// vol row layout: float2 per z, so a 16B-aligned float4 at even z covers (z, z+1).
__device__ __forceinline__ void row_fetch(const float4* __restrict__ v4,
                                          int row, int iz0, int iz1,
                                          float2& c0, float2& c1)
{
    int zb = iz0 & ~1;
    float4 q = __ldg(v4 + ((row + zb) >> 1));
    if ((iz0 & 1) == 0) {
        // even: q = [z0.ch0, z0.ch1, z1.ch0, z1.ch1]
        c0 = make_float2(q.x, q.y);
        c1 = make_float2(q.z, q.w);
    } else {
        // odd: q holds (zb, zb+1) = (iz0-1, iz0)
        c0 = make_float2(q.z, q.w);
        if (iz1 != iz0) {
            // iz1 = iz0+1 is even -> aligned float4 load, take first pair
            float4 q2 = __ldg(v4 + ((row + iz1) >> 1));
            c1 = make_float2(q2.x, q2.y);
        } else {
            c1 = c0;   // clamped at z = D3-1 (odd)
        }
    }
}

__global__ __launch_bounds__(256) void st_warp3d_kernel(
    const float*  __restrict__ vol,   // [D1,D2,D3,2] (batch 0)
    const float*  __restrict__ trf,   // [D1,D2,D3,3] (batch 0)
    float2*       __restrict__ out)
{
    int idx = blockIdx.x * blockDim.x + threadIdx.x;
    if (idx >= NVOX) return;

    int z  = idx % D3;
    int t  = idx / D3;
    int y  = t % D2;
    int x  = t / D2;

    const float* tp = trf + (size_t)idx * 3;
    float sx = __ldg(tp + 0);
    float sy = __ldg(tp + 1);
    float sz = __ldg(tp + 2);

    float lx = fminf(fmaxf((float)x + sx, 0.0f), (float)(D1 - 1));
    float ly = fminf(fmaxf((float)y + sy, 0.0f), (float)(D2 - 1));
    float lz = fminf(fmaxf((float)z + sz, 0.0f), (float)(D3 - 1));

    float fx = floorf(lx), fy = floorf(ly), fz = floorf(lz);
    int ix0 = (int)fx, iy0 = (int)fy, iz0 = (int)fz;
    int ix1 = min(ix0 + 1, D1 - 1);
    int iy1 = min(iy0 + 1, D2 - 1);
    int iz1 = min(iz0 + 1, D3 - 1);

    float wx1 = lx - fx, wx0 = 1.0f - wx1;
    float wy1 = ly - fy, wy0 = 1.0f - wy1;
    float wz1 = lz - fz, wz0 = 1.0f - wz1;

    const float4* v4 = (const float4*)vol;

    int r00 = (ix0 * D2 + iy0) * D3;
    int r01 = (ix0 * D2 + iy1) * D3;
    int r10 = (ix1 * D2 + iy0) * D3;
    int r11 = (ix1 * D2 + iy1) * D3;

    float2 a0, a1, b0, b1, c0, c1, d0, d1;
    row_fetch(v4, r00, iz0, iz1, a0, a1);
    row_fetch(v4, r01, iz0, iz1, b0, b1);
    row_fetch(v4, r10, iz0, iz1, c0, c1);
    row_fetch(v4, r11, iz0, iz1, d0, d1);

    // factored interpolation: z, then y, then x
    float e00x = a0.x * wz0 + a1.x * wz1;
    float e00y = a0.y * wz0 + a1.y * wz1;
    float e01x = b0.x * wz0 + b1.x * wz1;
    float e01y = b0.y * wz0 + b1.y * wz1;
    float e10x = c0.x * wz0 + c1.x * wz1;
    float e10y = c0.y * wz0 + c1.y * wz1;
    float e11x = d0.x * wz0 + d1.x * wz1;
    float e11y = d0.y * wz0 + d1.y * wz1;

    float f0x = e00x * wy0 + e01x * wy1;
    float f0y = e00y * wy0 + e01y * wy1;
    float f1x = e10x * wy0 + e11x * wy1;
    float f1y = e10y * wy0 + e11y * wy1;

    float2 acc;
    acc.x = f0x * wx0 + f1x * wx1;
    acc.y = f0y * wx0 + f1y * wx1;

    out[idx] = acc;
}

extern "C" void kernel_launch(void* const* d_in, const int* in_sizes, int n_in,
                              void* d_out, int out_size)
{
    const float* vol = (const float*)d_in[0];  // [2,160,192,224,2] -> batch 0
    const float* trf = (const float*)d_in[1];  // [2,160,192,224,3] -> batch 0
    float2* out = (float2*)d_out;

    int threads = 256;
    int blocks = (NVOX + threads - 1) / threads;
    st_warp3d_kernel<<<blocks, threads>>>(vol, trf, out);
}

// round 3
// speedup vs baseline: 1.1918x; 1.1918x over previous
#include <cuda_runtime.h>
#include <cstdint>

#define D1 160
#define D2 192
#define D3 224

static constexpr int NVOX = D1 * D2 * D3;   // 6,881,280

__global__ __launch_bounds__(256) void st_warp3d_kernel(
    const float*  __restrict__ vol,   // [D1,D2,D3,2] (batch 0)
    const float*  __restrict__ trf,   // [D1,D2,D3,3] (batch 0)
    float2*       __restrict__ out)
{
    int idx = blockIdx.x * blockDim.x + threadIdx.x;
    if (idx >= NVOX) return;

    int z  = idx % D3;
    int t  = idx / D3;
    int y  = t % D2;
    int x  = t / D2;

    // streaming read of the dense shift (no reuse -> evict-first)
    const float* tp = trf + (size_t)idx * 3;
    float sx = __ldcs(tp + 0);
    float sy = __ldcs(tp + 1);
    float sz = __ldcs(tp + 2);

    float lx = fminf(fmaxf((float)x + sx, 0.0f), (float)(D1 - 1));
    float ly = fminf(fmaxf((float)y + sy, 0.0f), (float)(D2 - 1));
    float lz = fminf(fmaxf((float)z + sz, 0.0f), (float)(D3 - 1));

    float fx = floorf(lx), fy = floorf(ly), fz = floorf(lz);
    int ix0 = (int)fx, iy0 = (int)fy, iz0 = (int)fz;
    int ix1 = min(ix0 + 1, D1 - 1);
    int iy1 = min(iy0 + 1, D2 - 1);
    int iz1 = min(iz0 + 1, D3 - 1);

    float wx1 = lx - fx, wx0 = 1.0f - wx1;
    float wy1 = ly - fy, wy0 = 1.0f - wy1;
    float wz1 = lz - fz, wz0 = 1.0f - wz1;

    const float4* v4 = (const float4*)vol;
    const float2* v2 = (const float2*)vol;

    int r00 = (ix0 * D2 + iy0) * D3;
    int r01 = (ix0 * D2 + iy1) * D3;
    int r10 = (ix1 * D2 + iy0) * D3;
    int r11 = (ix1 * D2 + iy1) * D3;

    int odd = iz0 & 1;
    int zb  = iz0 & ~1;           // aligned pair base: covers (zb, zb+1)

    // Per (x,y) row: one aligned 16B load gives both z-corners for even lanes;
    // odd lanes fix up corner1 with a single predicated 8B load (no branch).
    float2 c0[4], c1[4];
    int rows[4] = { r00, r01, r10, r11 };

#pragma unroll
    for (int r = 0; r < 4; r++) {
        float4 q = __ldg(v4 + ((rows[r] + zb) >> 1));
        // predicated odd-lane load of v2[row + iz1] (iz1 is even here, or ==iz0 at the top edge)
        float ex = 0.0f, ey = 0.0f;
        {
            const float2* ap = v2 + rows[r] + iz1;
            asm volatile(
                "{\n\t"
                ".reg .pred p;\n\t"
                "setp.ne.s32 p, %2, 0;\n\t"
                "@p ld.global.nc.v2.f32 {%0, %1}, [%3];\n\t"
                "}"
                : "+f"(ex), "+f"(ey)
                : "r"(odd), "l"(ap));
        }
        // branch-free selects
        c0[r].x = odd ? q.z : q.x;
        c0[r].y = odd ? q.w : q.y;
        c1[r].x = odd ? ex  : q.z;
        c1[r].y = odd ? ey  : q.w;
    }

    // factored interpolation: z, then y, then x
    float e00x = c0[0].x * wz0 + c1[0].x * wz1;
    float e00y = c0[0].y * wz0 + c1[0].y * wz1;
    float e01x = c0[1].x * wz0 + c1[1].x * wz1;
    float e01y = c0[1].y * wz0 + c1[1].y * wz1;
    float e10x = c0[2].x * wz0 + c1[2].x * wz1;
    float e10y = c0[2].y * wz0 + c1[2].y * wz1;
    float e11x = c0[3].x * wz0 + c1[3].x * wz1;
    float e11y = c0[3].y * wz0 + c1[3].y * wz1;

    float f0x = e00x * wy0 + e01x * wy1;
    float f0y = e00y * wy0 + e01y * wy1;
    float f1x = e10x * wy0 + e11x * wy1;
    float f1y = e10y * wy0 + e11y * wy1;

    float2 acc;
    acc.x = f0x * wx0 + f1x * wx1;
    acc.y = f0y * wx0 + f1y * wx1;

    // streaming store (output never re-read; keep L2 for vol)
    __stcs(&out[idx], acc);
}

extern "C" void kernel_launch(void* const* d_in, const int* in_sizes, int n_in,
                              void* d_out, int out_size)
{
    const float* vol = (const float*)d_in[0];  // [2,160,192,224,2] -> batch 0
    const float* trf = (const float*)d_in[1];  // [2,160,192,224,3] -> batch 0
    float2* out = (float2*)d_out;

    int threads = 256;
    int blocks = (NVOX + threads - 1) / threads;
    st_warp3d_kernel<<<blocks, threads>>>(vol, trf, out);
}